// round 4
// baseline (speedup 1.0000x reference)
#include <cuda_runtime.h>
#include <cuda_fp16.h>

#define CCH   32
#define R0_   128
#define R1_   512
#define GB_   64                     // bins per axis
#define NB_   (GB_ * GB_ * GB_)      // 262144 bins
#define MAXN  2200000

// Planes re-laid-out as [H*W, C] fp16 so one texel = 64B.
__device__ __half g_xy0[R0_ * R0_ * CCH];
__device__ __half g_xz0[R0_ * R0_ * CCH];
__device__ __half g_yz0[R0_ * R0_ * CCH];
__device__ __half g_xy1[R1_ * R1_ * CCH];
__device__ __half g_xz1[R1_ * R1_ * CCH];
__device__ __half g_yz1[R1_ * R1_ * CCH];

// Sorting scratch
__device__ int    g_hist[NB_];
__device__ int    g_cursor[NB_];
__device__ int    g_btot[NB_ / 1024];
__device__ int    g_bbase[NB_ / 1024];
__device__ float4 g_spts[MAXN];      // sorted (x,y,z, bitcast original idx)

// ---------------- transpose: [C, HW] fp32 -> [HW, C] fp16 ----------------
__global__ void transpose_kernel(const float* __restrict__ in,
                                 __half* __restrict__ out, int HW) {
    __shared__ float tile[32][33];
    int pix0 = blockIdx.x * 32;
    int tx = threadIdx.x, ty = threadIdx.y;
#pragma unroll
    for (int cc = 0; cc < 32; cc += 8)
        tile[cc + ty][tx] = in[(cc + ty) * HW + pix0 + tx];
    __syncthreads();
#pragma unroll
    for (int pp = 0; pp < 32; pp += 8)
        out[(pix0 + pp + ty) * CCH + tx] = __float2half(tile[tx][pp + ty]);
}

// ---------------- Morton key ----------------
__device__ __forceinline__ unsigned expand_bits(unsigned v) {
    v = (v * 0x00010001u) & 0xFF0000FFu;
    v = (v * 0x00000101u) & 0x0F00F00Fu;
    v = (v * 0x00000011u) & 0xC30C30C3u;
    v = (v * 0x00000005u) & 0x49249249u;
    return v;
}
__device__ __forceinline__ int point_key(float x, float y, float z) {
    int bx = min(max((int)((x + 1.0f) * (0.5f * GB_)), 0), GB_ - 1);
    int by = min(max((int)((y + 1.0f) * (0.5f * GB_)), 0), GB_ - 1);
    int bz = min(max((int)((z + 1.0f) * (0.5f * GB_)), 0), GB_ - 1);
    return (int)(expand_bits(bx) | (expand_bits(by) << 1) | (expand_bits(bz) << 2));
}

// ---------------- sort pipeline ----------------
__global__ void zero_hist_kernel() {
    int i = blockIdx.x * blockDim.x + threadIdx.x;
    if (i < NB_) g_hist[i] = 0;
}

__global__ void hist_kernel(const float* __restrict__ pts, int n) {
    int i = blockIdx.x * blockDim.x + threadIdx.x;
    if (i >= n) return;
    float x = pts[3 * i], y = pts[3 * i + 1], z = pts[3 * i + 2];
    atomicAdd(&g_hist[point_key(x, y, z)], 1);
}

// Per-1024-chunk exclusive scan; writes chunk totals.
__global__ void scan1_kernel() {
    __shared__ int warp_sums[32];
    int gid = blockIdx.x * 1024 + threadIdx.x;
    int lane = threadIdx.x & 31, wid = threadIdx.x >> 5;
    int v = g_hist[gid];
    int s = v;
#pragma unroll
    for (int o = 1; o < 32; o <<= 1) {
        int t = __shfl_up_sync(0xFFFFFFFFu, s, o);
        if (lane >= o) s += t;
    }
    if (lane == 31) warp_sums[wid] = s;
    __syncthreads();
    if (wid == 0) {
        int ws = warp_sums[lane];
#pragma unroll
        for (int o = 1; o < 32; o <<= 1) {
            int t = __shfl_up_sync(0xFFFFFFFFu, ws, o);
            if (lane >= o) ws += t;
        }
        warp_sums[lane] = ws;
    }
    __syncthreads();
    int add = (wid > 0) ? warp_sums[wid - 1] : 0;
    int incl = s + add;
    g_cursor[gid] = incl - v;   // exclusive within chunk
    if (threadIdx.x == 1023) g_btot[blockIdx.x] = incl;
}

// Exclusive scan of the 256 chunk totals.
__global__ void scan2_kernel() {
    __shared__ int sh[NB_ / 1024];
    int t = threadIdx.x;
    int v = g_btot[t];
    sh[t] = v;
    __syncthreads();
    for (int o = 1; o < NB_ / 1024; o <<= 1) {
        int val = sh[t];
        int add = (t >= o) ? sh[t - o] : 0;
        __syncthreads();
        sh[t] = val + add;
        __syncthreads();
    }
    g_bbase[t] = sh[t] - v;
}

__global__ void scatter_kernel(const float* __restrict__ pts, int n) {
    int i = blockIdx.x * blockDim.x + threadIdx.x;
    if (i >= n) return;
    float x = pts[3 * i], y = pts[3 * i + 1], z = pts[3 * i + 2];
    int key = point_key(x, y, z);
    int pos = g_bbase[key >> 10] + atomicAdd(&g_cursor[key], 1);
    g_spts[pos] = make_float4(x, y, z, __int_as_float(i));
}

// ---------------- bilerp ----------------
// L1CACHE=true  -> __ldg  (coarse planes: tiny per-block footprint, keep in L1)
// L1CACHE=false -> __ldcg (fine planes: streaming, bypass L1 so they don't
//                          evict the coarse working set)
template <bool L1CACHE>
__device__ __forceinline__ void bilerp8(const uint4* __restrict__ plane,
                                        int R, float gx, float gy, int q,
                                        float2 acc[4]) {
    float s = 0.5f * (float)(R - 1);
    float ix = fminf(fmaxf((gx + 1.0f) * s, 0.0f), (float)(R - 1));
    float iy = fminf(fmaxf((gy + 1.0f) * s, 0.0f), (float)(R - 1));
    float x0f = floorf(ix), y0f = floorf(iy);
    int x0 = (int)x0f, y0 = (int)y0f;
    int x1 = min(x0 + 1, R - 1);
    int y1 = min(y0 + 1, R - 1);
    float wx = ix - x0f, wy = iy - y0f;

    float w00 = (1.0f - wx) * (1.0f - wy);
    float w10 = wx * (1.0f - wy);
    float w01 = (1.0f - wx) * wy;
    float w11 = wx * wy;

    uint4 v00, v10, v01, v11;
    if (L1CACHE) {
        v00 = __ldg(plane + ((long)y0 * R + x0) * 4 + q);
        v10 = __ldg(plane + ((long)y0 * R + x1) * 4 + q);
        v01 = __ldg(plane + ((long)y1 * R + x0) * 4 + q);
        v11 = __ldg(plane + ((long)y1 * R + x1) * 4 + q);
    } else {
        v00 = __ldcg(plane + ((long)y0 * R + x0) * 4 + q);
        v10 = __ldcg(plane + ((long)y0 * R + x1) * 4 + q);
        v01 = __ldcg(plane + ((long)y1 * R + x0) * 4 + q);
        v11 = __ldcg(plane + ((long)y1 * R + x1) * 4 + q);
    }

    const __half2* h00 = (const __half2*)&v00;
    const __half2* h10 = (const __half2*)&v10;
    const __half2* h01 = (const __half2*)&v01;
    const __half2* h11 = (const __half2*)&v11;

#pragma unroll
    for (int i = 0; i < 4; i++) {
        float2 f00 = __half22float2(h00[i]);
        float2 f10 = __half22float2(h10[i]);
        float2 f01 = __half22float2(h01[i]);
        float2 f11 = __half22float2(h11[i]);
        acc[i].x += f00.x * w00 + f10.x * w10 + f01.x * w01 + f11.x * w11;
        acc[i].y += f00.y * w00 + f10.y * w10 + f01.y * w01 + f11.y * w11;
    }
}

__device__ __forceinline__ void gather_point(float x, float y, float z, int q,
                                             float* __restrict__ outrow) {
    float2 a0[4] = {{0.f,0.f},{0.f,0.f},{0.f,0.f},{0.f,0.f}};
    float2 a1[4] = {{0.f,0.f},{0.f,0.f},{0.f,0.f},{0.f,0.f}};

    // coarse: L1-cached (high reuse after Morton sort)
    bilerp8<true>((const uint4*)g_xy0, R0_, x, y, q, a0);
    bilerp8<true>((const uint4*)g_xz0, R0_, x, z, q, a0);
    bilerp8<true>((const uint4*)g_yz0, R0_, y, z, q, a0);
    // fine: streaming, bypass L1
    bilerp8<false>((const uint4*)g_xy1, R1_, x, y, q, a1);
    bilerp8<false>((const uint4*)g_xz1, R1_, x, z, q, a1);
    bilerp8<false>((const uint4*)g_yz1, R1_, y, z, q, a1);

    float4* o = (float4*)outrow;
    __stcs(&o[q * 2 + 0],     make_float4(a0[0].x, a0[0].y, a0[1].x, a0[1].y));
    __stcs(&o[q * 2 + 1],     make_float4(a0[2].x, a0[2].y, a0[3].x, a0[3].y));
    __stcs(&o[8 + q * 2 + 0], make_float4(a1[0].x, a1[0].y, a1[1].x, a1[1].y));
    __stcs(&o[8 + q * 2 + 1], make_float4(a1[2].x, a1[2].y, a1[3].x, a1[3].y));
}

// Sorted gather: 512 threads = 128 points/block, 4 threads/point.
__global__ void __launch_bounds__(512)
gather_sorted_kernel(float* __restrict__ out, int n) {
    int p = blockIdx.x * 128 + (threadIdx.x >> 2);
    int q = threadIdx.x & 3;
    if (p >= n) return;
    float4 pt = __ldg(&g_spts[p]);
    int oi = __float_as_int(pt.w);
    gather_point(pt.x, pt.y, pt.z, q, out + (long)oi * 64);
}

// Fallback (n > MAXN): direct unsorted gather.
__global__ void gather_direct_kernel(const float* __restrict__ pts,
                                     float* __restrict__ out, int n) {
    int tid = blockIdx.x * blockDim.x + threadIdx.x;
    int p = tid >> 2;
    int q = tid & 3;
    if (p >= n) return;
    float x = __ldg(pts + (long)p * 3 + 0);
    float y = __ldg(pts + (long)p * 3 + 1);
    float z = __ldg(pts + (long)p * 3 + 2);
    gather_point(x, y, z, q, out + (long)p * 64);
}

extern "C" void kernel_launch(void* const* d_in, const int* in_sizes, int n_in,
                              void* d_out, int out_size) {
    const float* pts = (const float*)d_in[0];
    int n = in_sizes[0] / 3;

    __half *xy0, *xz0, *yz0, *xy1, *xz1, *yz1;
    cudaGetSymbolAddress((void**)&xy0, g_xy0);
    cudaGetSymbolAddress((void**)&xz0, g_xz0);
    cudaGetSymbolAddress((void**)&yz0, g_yz0);
    cudaGetSymbolAddress((void**)&xy1, g_xy1);
    cudaGetSymbolAddress((void**)&xz1, g_xz1);
    cudaGetSymbolAddress((void**)&yz1, g_yz1);

    dim3 tb(32, 8);
    int hw0 = R0_ * R0_, hw1 = R1_ * R1_;
    transpose_kernel<<<hw0 / 32, tb>>>((const float*)d_in[1], xy0, hw0);
    transpose_kernel<<<hw0 / 32, tb>>>((const float*)d_in[2], xz0, hw0);
    transpose_kernel<<<hw0 / 32, tb>>>((const float*)d_in[3], yz0, hw0);
    transpose_kernel<<<hw1 / 32, tb>>>((const float*)d_in[4], xy1, hw1);
    transpose_kernel<<<hw1 / 32, tb>>>((const float*)d_in[5], xz1, hw1);
    transpose_kernel<<<hw1 / 32, tb>>>((const float*)d_in[6], yz1, hw1);

    if (n <= MAXN) {
        zero_hist_kernel<<<NB_ / 1024, 1024>>>();
        hist_kernel<<<(n + 255) / 256, 256>>>(pts, n);
        scan1_kernel<<<NB_ / 1024, 1024>>>();
        scan2_kernel<<<1, NB_ / 1024>>>();
        scatter_kernel<<<(n + 255) / 256, 256>>>(pts, n);
        gather_sorted_kernel<<<(n + 127) / 128, 512>>>((float*)d_out, n);
    } else {
        long total = (long)n * 4;
        int blocks = (int)((total + 511) / 512);
        gather_direct_kernel<<<blocks, 512>>>(pts, (float*)d_out, n);
    }
}

// round 5
// speedup vs baseline: 1.3750x; 1.3750x over previous
#include <cuda_runtime.h>
#include <cuda_fp16.h>

#define CCH   32
#define R0_   128
#define R1_   512
#define HW0   (R0_ * R0_)
#define HW1   (R1_ * R1_)

// Planes re-laid-out as [H*W, C] fp16 so one texel = 64B.
__device__ __half g_xy0[HW0 * CCH];
__device__ __half g_xz0[HW0 * CCH];
__device__ __half g_yz0[HW0 * CCH];
__device__ __half g_xy1[HW1 * CCH];
__device__ __half g_xz1[HW1 * CCH];
__device__ __half g_yz1[HW1 * CCH];

#define TILES0 (HW0 / 32)            // 512 tiles per small plane
#define TILES1 (HW1 / 32)            // 8192 tiles per big plane
#define TILES_ALL (3 * TILES0 + 3 * TILES1)

// One fused transpose over all 6 planes: [C, HW] fp32 -> [HW, C] fp16.
// Block (32,8): tile of 32 channels x 32 pixels.
__global__ void transpose_all_kernel(const float* __restrict__ in0,
                                     const float* __restrict__ in1,
                                     const float* __restrict__ in2,
                                     const float* __restrict__ in3,
                                     const float* __restrict__ in4,
                                     const float* __restrict__ in5,
                                     __half* __restrict__ o0,
                                     __half* __restrict__ o1,
                                     __half* __restrict__ o2,
                                     __half* __restrict__ o3,
                                     __half* __restrict__ o4,
                                     __half* __restrict__ o5) {
    __shared__ float tile[32][33];
    int bid = blockIdx.x;

    const float* in;
    __half* out;
    int HW, pix0;
    if (bid < 3 * TILES0) {
        int plane = bid / TILES0;
        pix0 = (bid % TILES0) * 32;
        HW = HW0;
        in  = plane == 0 ? in0 : (plane == 1 ? in1 : in2);
        out = plane == 0 ? o0  : (plane == 1 ? o1  : o2);
    } else {
        int b = bid - 3 * TILES0;
        int plane = b / TILES1;
        pix0 = (b % TILES1) * 32;
        HW = HW1;
        in  = plane == 0 ? in3 : (plane == 1 ? in4 : in5);
        out = plane == 0 ? o3  : (plane == 1 ? o4  : o5);
    }

    int tx = threadIdx.x, ty = threadIdx.y;
#pragma unroll
    for (int cc = 0; cc < 32; cc += 8)
        tile[cc + ty][tx] = in[(cc + ty) * HW + pix0 + tx];
    __syncthreads();
#pragma unroll
    for (int pp = 0; pp < 32; pp += 8)
        out[(pix0 + pp + ty) * CCH + tx] = __float2half(tile[tx][pp + ty]);
}

// ---------------- bilerp: one 8-channel quad from a [HW, 32] fp16 plane ----
__device__ __forceinline__ void bilerp8(const uint4* __restrict__ plane,
                                        int R, float gx, float gy, int q,
                                        float2 acc[4]) {
    float s = 0.5f * (float)(R - 1);
    float ix = fminf(fmaxf((gx + 1.0f) * s, 0.0f), (float)(R - 1));
    float iy = fminf(fmaxf((gy + 1.0f) * s, 0.0f), (float)(R - 1));
    float x0f = floorf(ix), y0f = floorf(iy);
    int x0 = (int)x0f, y0 = (int)y0f;
    int x1 = min(x0 + 1, R - 1);
    int y1 = min(y0 + 1, R - 1);
    float wx = ix - x0f, wy = iy - y0f;

    float w00 = (1.0f - wx) * (1.0f - wy);
    float w10 = wx * (1.0f - wy);
    float w01 = (1.0f - wx) * wy;
    float w11 = wx * wy;

    uint4 v00 = __ldg(plane + ((long)y0 * R + x0) * 4 + q);
    uint4 v10 = __ldg(plane + ((long)y0 * R + x1) * 4 + q);
    uint4 v01 = __ldg(plane + ((long)y1 * R + x0) * 4 + q);
    uint4 v11 = __ldg(plane + ((long)y1 * R + x1) * 4 + q);

    const __half2* h00 = (const __half2*)&v00;
    const __half2* h10 = (const __half2*)&v10;
    const __half2* h01 = (const __half2*)&v01;
    const __half2* h11 = (const __half2*)&v11;

#pragma unroll
    for (int i = 0; i < 4; i++) {
        float2 f00 = __half22float2(h00[i]);
        float2 f10 = __half22float2(h10[i]);
        float2 f01 = __half22float2(h01[i]);
        float2 f11 = __half22float2(h11[i]);
        acc[i].x += f00.x * w00 + f10.x * w10 + f01.x * w01 + f11.x * w11;
        acc[i].y += f00.y * w00 + f10.y * w10 + f01.y * w01 + f11.y * w11;
    }
}

// 4 threads per point; thread q handles channels [8q, 8q+8) of both levels.
__global__ void gather_kernel(const float* __restrict__ pts,
                              float* __restrict__ out, int n) {
    int tid = blockIdx.x * blockDim.x + threadIdx.x;
    int p = tid >> 2;
    int q = tid & 3;
    if (p >= n) return;

    float x = __ldg(pts + (long)p * 3 + 0);
    float y = __ldg(pts + (long)p * 3 + 1);
    float z = __ldg(pts + (long)p * 3 + 2);

    float2 a0[4] = {{0.f,0.f},{0.f,0.f},{0.f,0.f},{0.f,0.f}};
    float2 a1[4] = {{0.f,0.f},{0.f,0.f},{0.f,0.f},{0.f,0.f}};

    bilerp8((const uint4*)g_xy0, R0_, x, y, q, a0);
    bilerp8((const uint4*)g_xz0, R0_, x, z, q, a0);
    bilerp8((const uint4*)g_yz0, R0_, y, z, q, a0);
    bilerp8((const uint4*)g_xy1, R1_, x, y, q, a1);
    bilerp8((const uint4*)g_xz1, R1_, x, z, q, a1);
    bilerp8((const uint4*)g_yz1, R1_, y, z, q, a1);

    float4* o = (float4*)(out + (long)p * 64);
    o[q * 2 + 0]     = make_float4(a0[0].x, a0[0].y, a0[1].x, a0[1].y);
    o[q * 2 + 1]     = make_float4(a0[2].x, a0[2].y, a0[3].x, a0[3].y);
    o[8 + q * 2 + 0] = make_float4(a1[0].x, a1[0].y, a1[1].x, a1[1].y);
    o[8 + q * 2 + 1] = make_float4(a1[2].x, a1[2].y, a1[3].x, a1[3].y);
}

extern "C" void kernel_launch(void* const* d_in, const int* in_sizes, int n_in,
                              void* d_out, int out_size) {
    const float* pts = (const float*)d_in[0];
    int n = in_sizes[0] / 3;

    __half *xy0, *xz0, *yz0, *xy1, *xz1, *yz1;
    cudaGetSymbolAddress((void**)&xy0, g_xy0);
    cudaGetSymbolAddress((void**)&xz0, g_xz0);
    cudaGetSymbolAddress((void**)&yz0, g_yz0);
    cudaGetSymbolAddress((void**)&xy1, g_xy1);
    cudaGetSymbolAddress((void**)&xz1, g_xz1);
    cudaGetSymbolAddress((void**)&yz1, g_yz1);

    dim3 tb(32, 8);
    transpose_all_kernel<<<TILES_ALL, tb>>>(
        (const float*)d_in[1], (const float*)d_in[2], (const float*)d_in[3],
        (const float*)d_in[4], (const float*)d_in[5], (const float*)d_in[6],
        xy0, xz0, yz0, xy1, xz1, yz1);

    int threads = 256;
    long total = (long)n * 4;
    int blocks = (int)((total + threads - 1) / threads);
    gather_kernel<<<blocks, threads>>>(pts, (float*)d_out, n);
}

// round 6
// speedup vs baseline: 1.4025x; 1.0200x over previous
#include <cuda_runtime.h>
#include <cuda_fp16.h>

#define CCH   32
#define R0_   128
#define R1_   512
#define HW0   (R0_ * R0_)
#define HW1   (R1_ * R1_)

// Planes re-laid-out as [H*W, C] fp16 so one texel = 64B.
__device__ __half g_xy0[HW0 * CCH];
__device__ __half g_xz0[HW0 * CCH];
__device__ __half g_yz0[HW0 * CCH];
__device__ __half g_xy1[HW1 * CCH];
__device__ __half g_xz1[HW1 * CCH];
__device__ __half g_yz1[HW1 * CCH];

#define TILES0 (HW0 / 32)
#define TILES1 (HW1 / 32)
#define TILES_ALL (3 * TILES0 + 3 * TILES1)

// One fused transpose over all 6 planes: [C, HW] fp32 -> [HW, C] fp16.
__global__ void transpose_all_kernel(const float* __restrict__ in0,
                                     const float* __restrict__ in1,
                                     const float* __restrict__ in2,
                                     const float* __restrict__ in3,
                                     const float* __restrict__ in4,
                                     const float* __restrict__ in5,
                                     __half* __restrict__ o0,
                                     __half* __restrict__ o1,
                                     __half* __restrict__ o2,
                                     __half* __restrict__ o3,
                                     __half* __restrict__ o4,
                                     __half* __restrict__ o5) {
    __shared__ float tile[32][33];
    int bid = blockIdx.x;

    const float* in;
    __half* out;
    int HW, pix0;
    if (bid < 3 * TILES0) {
        int plane = bid / TILES0;
        pix0 = (bid % TILES0) * 32;
        HW = HW0;
        in  = plane == 0 ? in0 : (plane == 1 ? in1 : in2);
        out = plane == 0 ? o0  : (plane == 1 ? o1  : o2);
    } else {
        int b = bid - 3 * TILES0;
        int plane = b / TILES1;
        pix0 = (b % TILES1) * 32;
        HW = HW1;
        in  = plane == 0 ? in3 : (plane == 1 ? in4 : in5);
        out = plane == 0 ? o3  : (plane == 1 ? o4  : o5);
    }

    int tx = threadIdx.x, ty = threadIdx.y;
#pragma unroll
    for (int cc = 0; cc < 32; cc += 8)
        tile[cc + ty][tx] = in[(cc + ty) * HW + pix0 + tx];
    __syncthreads();
#pragma unroll
    for (int pp = 0; pp < 32; pp += 8)
        out[(pix0 + pp + ty) * CCH + tx] = __float2half(tile[tx][pp + ty]);
}

// ---------------- bilerp: one 8-channel quad from a [HW, 32] fp16 plane ----
__device__ __forceinline__ void bilerp8(const uint4* __restrict__ plane,
                                        int R, float gx, float gy, int q,
                                        float2 acc[4]) {
    float s = 0.5f * (float)(R - 1);
    float ix = fminf(fmaxf((gx + 1.0f) * s, 0.0f), (float)(R - 1));
    float iy = fminf(fmaxf((gy + 1.0f) * s, 0.0f), (float)(R - 1));
    float x0f = floorf(ix), y0f = floorf(iy);
    int x0 = (int)x0f, y0 = (int)y0f;
    int x1 = min(x0 + 1, R - 1);
    int y1 = min(y0 + 1, R - 1);
    float wx = ix - x0f, wy = iy - y0f;

    float w00 = (1.0f - wx) * (1.0f - wy);
    float w10 = wx * (1.0f - wy);
    float w01 = (1.0f - wx) * wy;
    float w11 = wx * wy;

    uint4 v00 = __ldg(plane + ((long)y0 * R + x0) * 4 + q);
    uint4 v10 = __ldg(plane + ((long)y0 * R + x1) * 4 + q);
    uint4 v01 = __ldg(plane + ((long)y1 * R + x0) * 4 + q);
    uint4 v11 = __ldg(plane + ((long)y1 * R + x1) * 4 + q);

    const __half2* h00 = (const __half2*)&v00;
    const __half2* h10 = (const __half2*)&v10;
    const __half2* h01 = (const __half2*)&v01;
    const __half2* h11 = (const __half2*)&v11;

#pragma unroll
    for (int i = 0; i < 4; i++) {
        float2 f00 = __half22float2(h00[i]);
        float2 f10 = __half22float2(h10[i]);
        float2 f01 = __half22float2(h01[i]);
        float2 f11 = __half22float2(h11[i]);
        acc[i].x += f00.x * w00 + f10.x * w10 + f01.x * w01 + f11.x * w11;
        acc[i].y += f00.y * w00 + f10.y * w10 + f01.y * w01 + f11.y * w11;
    }
}

// Coarse gather: samples the three 128^2 planes, writes out floats [0,32).
__global__ void __launch_bounds__(256)
gather_coarse_kernel(const float* __restrict__ pts,
                     float* __restrict__ out, int n) {
    int tid = blockIdx.x * blockDim.x + threadIdx.x;
    int p = tid >> 2;
    int q = tid & 3;
    if (p >= n) return;

    float x = __ldg(pts + (long)p * 3 + 0);
    float y = __ldg(pts + (long)p * 3 + 1);
    float z = __ldg(pts + (long)p * 3 + 2);

    float2 a[4] = {{0.f,0.f},{0.f,0.f},{0.f,0.f},{0.f,0.f}};
    bilerp8((const uint4*)g_xy0, R0_, x, y, q, a);
    bilerp8((const uint4*)g_xz0, R0_, x, z, q, a);
    bilerp8((const uint4*)g_yz0, R0_, y, z, q, a);

    float4* o = (float4*)(out + (long)p * 64);
    o[q * 2 + 0] = make_float4(a[0].x, a[0].y, a[1].x, a[1].y);
    o[q * 2 + 1] = make_float4(a[2].x, a[2].y, a[3].x, a[3].y);
}

// Fine gather: samples the three 512^2 planes, writes out floats [32,64).
__global__ void __launch_bounds__(256)
gather_fine_kernel(const float* __restrict__ pts,
                   float* __restrict__ out, int n) {
    int tid = blockIdx.x * blockDim.x + threadIdx.x;
    int p = tid >> 2;
    int q = tid & 3;
    if (p >= n) return;

    float x = __ldg(pts + (long)p * 3 + 0);
    float y = __ldg(pts + (long)p * 3 + 1);
    float z = __ldg(pts + (long)p * 3 + 2);

    float2 a[4] = {{0.f,0.f},{0.f,0.f},{0.f,0.f},{0.f,0.f}};
    bilerp8((const uint4*)g_xy1, R1_, x, y, q, a);
    bilerp8((const uint4*)g_xz1, R1_, x, z, q, a);
    bilerp8((const uint4*)g_yz1, R1_, y, z, q, a);

    float4* o = (float4*)(out + (long)p * 64);
    o[8 + q * 2 + 0] = make_float4(a[0].x, a[0].y, a[1].x, a[1].y);
    o[8 + q * 2 + 1] = make_float4(a[2].x, a[2].y, a[3].x, a[3].y);
}

extern "C" void kernel_launch(void* const* d_in, const int* in_sizes, int n_in,
                              void* d_out, int out_size) {
    const float* pts = (const float*)d_in[0];
    int n = in_sizes[0] / 3;

    __half *xy0, *xz0, *yz0, *xy1, *xz1, *yz1;
    cudaGetSymbolAddress((void**)&xy0, g_xy0);
    cudaGetSymbolAddress((void**)&xz0, g_xz0);
    cudaGetSymbolAddress((void**)&yz0, g_yz0);
    cudaGetSymbolAddress((void**)&xy1, g_xy1);
    cudaGetSymbolAddress((void**)&xz1, g_xz1);
    cudaGetSymbolAddress((void**)&yz1, g_yz1);

    dim3 tb(32, 8);
    transpose_all_kernel<<<TILES_ALL, tb>>>(
        (const float*)d_in[1], (const float*)d_in[2], (const float*)d_in[3],
        (const float*)d_in[4], (const float*)d_in[5], (const float*)d_in[6],
        xy0, xz0, yz0, xy1, xz1, yz1);

    int threads = 256;
    long total = (long)n * 4;
    int blocks = (int)((total + threads - 1) / threads);
    gather_fine_kernel<<<blocks, threads>>>(pts, (float*)d_out, n);
    gather_coarse_kernel<<<blocks, threads>>>(pts, (float*)d_out, n);
}